// round 3
// baseline (speedup 1.0000x reference)
#include <cuda_runtime.h>

// Problem constants
#define T_TOKENS 16384      // 4 * 4096
#define DMODEL   2048
#define NEXP     64
#define MT       64         // tokens per block
#define BK       32         // k-chunk
#define KT       (DMODEL / BK)   // 64 k-tiles
#define ROWP     68         // padded smem row (64 + 4), multiple of 4 for float4

// Output layout (flattened reference return order, fp32)
#define OFF_W    ((size_t)0)                       // top_k_weights  [16384,2]
#define OFF_I    ((size_t)32768)                   // top_k_indices  [16384,2] (as float)
#define OFF_P    ((size_t)65536)                   // router_probs   [16384,64]
#define OFF_ENT  ((size_t)1114112)                 // routing_entropy scalar
#define OFF_CONF ((size_t)1114113)                 // selection_confidence scalar
#define OFF_UTIL ((size_t)1114114)                 // expert_utilization [64]

// Global accumulators (zeroed each launch by zero_kernel -> graph-replay safe)
__device__ float g_ent;
__device__ float g_conf;
__device__ int   g_counts[NEXP];

__global__ void zero_kernel() {
    int t = threadIdx.x;
    if (t == 0) { g_ent = 0.0f; g_conf = 0.0f; }
    if (t < NEXP) g_counts[t] = 0;
}

__global__ __launch_bounds__(256, 2)
void router_kernel(const float* __restrict__ x,
                   const float* __restrict__ W,
                   float* __restrict__ out)
{
    // sh holds xs[BK][ROWP] then ws[BK][ROWP] during GEMM (2*32*68 = 4352 floats),
    // reused as logits L[64][ROWP] for the epilogue (64*68 = 4352 floats).
    __shared__ float sh[2 * BK * ROWP];
    __shared__ float red[64];
    __shared__ int   hist[NEXP];

    const int t  = threadIdx.x;
    const int tx = t & 15;        // expert group: experts tx*4 .. tx*4+3
    const int ty = t >> 4;        // token group:  tokens ty*4 .. ty*4+3
    const int m0 = blockIdx.x * MT;

    if (t < NEXP) hist[t] = 0;

    float acc[4][4];
    #pragma unroll
    for (int i = 0; i < 4; i++)
        #pragma unroll
        for (int j = 0; j < 4; j++) acc[i][j] = 0.0f;

    // Tile load assignment: 512 float4 per operand tile, 2 per thread.
    // idx -> row (token/expert) = idx>>3, kq (float4 within 32-k chunk) = idx&7
    const int r0 = t >> 3,        k0q = t & 7;
    const int r1 = (t + 256) >> 3, k1q = (t + 256) & 7;

    float4 px0, px1, pw0, pw1;

    // Prefetch k-tile 0
    {
        px0 = *(const float4*)&x[(size_t)(m0 + r0) * DMODEL + k0q * 4];
        px1 = *(const float4*)&x[(size_t)(m0 + r1) * DMODEL + k1q * 4];
        pw0 = *(const float4*)&W[(size_t)r0 * DMODEL + k0q * 4];
        pw1 = *(const float4*)&W[(size_t)r1 * DMODEL + k1q * 4];
    }

    for (int kt = 0; kt < KT; kt++) {
        __syncthreads();   // previous compute done before smem overwrite

        // Store staged registers -> smem (k-major, transposed)
        sh[(k0q * 4 + 0) * ROWP + r0] = px0.x;
        sh[(k0q * 4 + 1) * ROWP + r0] = px0.y;
        sh[(k0q * 4 + 2) * ROWP + r0] = px0.z;
        sh[(k0q * 4 + 3) * ROWP + r0] = px0.w;
        sh[(k1q * 4 + 0) * ROWP + r1] = px1.x;
        sh[(k1q * 4 + 1) * ROWP + r1] = px1.y;
        sh[(k1q * 4 + 2) * ROWP + r1] = px1.z;
        sh[(k1q * 4 + 3) * ROWP + r1] = px1.w;

        float* ws = sh + BK * ROWP;
        ws[(k0q * 4 + 0) * ROWP + r0] = pw0.x;
        ws[(k0q * 4 + 1) * ROWP + r0] = pw0.y;
        ws[(k0q * 4 + 2) * ROWP + r0] = pw0.z;
        ws[(k0q * 4 + 3) * ROWP + r0] = pw0.w;
        ws[(k1q * 4 + 0) * ROWP + r1] = pw1.x;
        ws[(k1q * 4 + 1) * ROWP + r1] = pw1.y;
        ws[(k1q * 4 + 2) * ROWP + r1] = pw1.z;
        ws[(k1q * 4 + 3) * ROWP + r1] = pw1.w;

        __syncthreads();

        // Prefetch next k-tile while computing this one
        if (kt + 1 < KT) {
            const int kb = (kt + 1) * BK;
            px0 = *(const float4*)&x[(size_t)(m0 + r0) * DMODEL + kb + k0q * 4];
            px1 = *(const float4*)&x[(size_t)(m0 + r1) * DMODEL + kb + k1q * 4];
            pw0 = *(const float4*)&W[(size_t)r0 * DMODEL + kb + k0q * 4];
            pw1 = *(const float4*)&W[(size_t)r1 * DMODEL + kb + k1q * 4];
        }

        #pragma unroll
        for (int k = 0; k < BK; k++) {
            float4 a = *(const float4*)&sh[k * ROWP + ty * 4];
            float4 b = *(const float4*)&sh[BK * ROWP + k * ROWP + tx * 4];
            acc[0][0] += a.x * b.x;  acc[0][1] += a.x * b.y;
            acc[0][2] += a.x * b.z;  acc[0][3] += a.x * b.w;
            acc[1][0] += a.y * b.x;  acc[1][1] += a.y * b.y;
            acc[1][2] += a.y * b.z;  acc[1][3] += a.y * b.w;
            acc[2][0] += a.z * b.x;  acc[2][1] += a.z * b.y;
            acc[2][2] += a.z * b.z;  acc[2][3] += a.z * b.w;
            acc[3][0] += a.w * b.x;  acc[3][1] += a.w * b.y;
            acc[3][2] += a.w * b.z;  acc[3][3] += a.w * b.w;
        }
    }

    // ---- Epilogue: dump logits to smem (reuse sh) ----
    __syncthreads();
    #pragma unroll
    for (int i = 0; i < 4; i++) {
        float4 v = make_float4(acc[i][0], acc[i][1], acc[i][2], acc[i][3]);
        *(float4*)&sh[(ty * 4 + i) * ROWP + tx * 4] = v;
    }
    __syncthreads();

    float ent = 0.0f, conf = 0.0f;
    if (t < MT) {
        const int tok = m0 + t;
        float* L = &sh[t * ROWP];

        // top-2 (strict > keeps lowest index on exact ties, matching jax top_k)
        float m1 = -1e30f, m2 = -1e30f;
        int   i1 = 0, i2 = 0;
        #pragma unroll
        for (int e = 0; e < NEXP; e++) {
            float v = L[e];
            if (v > m1)       { m2 = m1; i2 = i1; m1 = v; i1 = e; }
            else if (v > m2)  { m2 = v;  i2 = e; }
        }

        // softmax pass 1: exponentials + Z (stash exps back into L)
        float Z = 0.0f;
        #pragma unroll 8
        for (int e = 0; e < NEXP; e++) {
            float ex = __expf(L[e] - m1);
            L[e] = ex;
            Z += ex;
        }
        float invZ = 1.0f / Z;

        // softmax pass 2: probs + entropy
        float* probs = out + OFF_P + (size_t)tok * NEXP;
        #pragma unroll 8
        for (int e = 0; e < NEXP; e++) {
            float p = L[e] * invZ;
            probs[e] = p;
            ent -= p * __logf(p + 1e-10f);
        }

        // top-2 renormalized weights: softmax([m1, m2])
        float ed = __expf(m2 - m1);          // <= 1
        float w0 = 1.0f / (1.0f + ed);
        float w1 = ed * w0;
        out[OFF_W + (size_t)tok * 2 + 0] = w0;
        out[OFF_W + (size_t)tok * 2 + 1] = w1;
        out[OFF_I + (size_t)tok * 2 + 0] = (float)i1;
        out[OFF_I + (size_t)tok * 2 + 1] = (float)i2;
        conf = w0;

        atomicAdd(&hist[i1], 1);
        atomicAdd(&hist[i2], 1);
    }

    // Block-reduce entropy -> global
    if (t < 64) red[t] = ent;
    __syncthreads();
    if (t < 32) {
        float v = red[t] + red[t + 32];
        #pragma unroll
        for (int o = 16; o > 0; o >>= 1) v += __shfl_down_sync(0xffffffffu, v, o);
        if (t == 0) atomicAdd(&g_ent, v);
    }
    __syncthreads();

    // Block-reduce confidence -> global
    if (t < 64) red[t] = conf;
    __syncthreads();
    if (t < 32) {
        float v = red[t] + red[t + 32];
        #pragma unroll
        for (int o = 16; o > 0; o >>= 1) v += __shfl_down_sync(0xffffffffu, v, o);
        if (t == 0) atomicAdd(&g_conf, v);
    }

    // Histogram -> global
    if (t < NEXP) {
        int c = hist[t];
        if (c) atomicAdd(&g_counts[t], c);
    }
}

__global__ void finalize_kernel(float* __restrict__ out) {
    int t = threadIdx.x;
    if (t == 0) {
        out[OFF_ENT]  = g_ent  * (1.0f / 16384.0f);
        out[OFF_CONF] = g_conf * (1.0f / 16384.0f);
    }
    if (t < NEXP) {
        // counts.sum() = 32768.0f in fp32; + 1e-10 is absorbed
        out[OFF_UTIL + t] = (float)g_counts[t] * (1.0f / 32768.0f);
    }
}

extern "C" void kernel_launch(void* const* d_in, const int* in_sizes, int n_in,
                              void* d_out, int out_size) {
    const float* x = (const float*)d_in[0];     // [4,4096,2048] fp32
    const float* W = (const float*)d_in[1];     // [64,2048] fp32
    float* out = (float*)d_out;

    zero_kernel<<<1, 64>>>();
    router_kernel<<<T_TOKENS / MT, 256>>>(x, W, out);
    finalize_kernel<<<1, 64>>>(out);
}

// round 5
// speedup vs baseline: 2.2160x; 2.2160x over previous
#include <cuda_runtime.h>
#include <cuda_fp16.h>
#include <cstdint>

// ---------------- problem constants ----------------
#define T_TOKENS 16384
#define DMODEL   2048
#define NEXP     64
#define MT       128
#define NCTAS    (T_TOKENS / MT)      // 128
#define BK       32
#define KT       (DMODEL / BK)        // 64
#define SCALE    2048.0f
#define INVS     (1.0f / 2048.0f)

// ---------------- output layout (fp32, reference return order) ----------------
#define OFF_W    ((size_t)0)
#define OFF_I    ((size_t)32768)
#define OFF_P    ((size_t)65536)
#define OFF_ENT  ((size_t)1114112)
#define OFF_CONF ((size_t)1114113)
#define OFF_UTIL ((size_t)1114114)

// ---------------- smem layout ----------------
// A/B rows padded to 80B (40 halves): bank stride 20 -> 8 consecutive rows hit
// 8 distinct bank groups => conflict-free ldmatrix without XOR swizzle.
#define ASTR     80
#define AH_OFF   0
#define AM_OFF   (128 * ASTR)             // 10240
#define BH_OFF   (2 * 128 * ASTR)         // 20480
#define BM_OFF   (BH_OFF + 64 * ASTR)     // 25600
#define BUF_BYTES (BH_OFF + 2 * 64 * ASTR)  // 30720
#define DSM_BYTES (2 * BUF_BYTES)           // 61440
#define LSTR     66                         // logits row stride (floats)

// ---------------- device globals ----------------
__device__ __half g_Wh[NEXP * DMODEL];
__device__ __half g_Wm[NEXP * DMODEL];
__device__ float  g_ent;
__device__ float  g_conf;
__device__ int    g_counts[NEXP];

// ---------------- helpers ----------------
__device__ __forceinline__ uint32_t smem_u32(const void* p) {
    uint32_t a;
    asm("{ .reg .u64 t; cvta.to.shared.u64 t, %1; cvt.u32.u64 %0, t; }" : "=r"(a) : "l"(p));
    return a;
}
#define STS128(addr, a, b, c, d) \
    asm volatile("st.shared.v4.b32 [%0], {%1,%2,%3,%4};" :: "r"(addr), "r"(a), "r"(b), "r"(c), "r"(d) : "memory")

__device__ __forceinline__ void ldsm4(uint32_t& r0, uint32_t& r1, uint32_t& r2, uint32_t& r3, uint32_t a) {
    asm volatile("ldmatrix.sync.aligned.m8n8.x4.shared.b16 {%0,%1,%2,%3}, [%4];"
                 : "=r"(r0), "=r"(r1), "=r"(r2), "=r"(r3) : "r"(a));
}
__device__ __forceinline__ void mma16816(float* c, const uint32_t* a, const uint32_t* b) {
    asm volatile("mma.sync.aligned.m16n8k16.row.col.f32.f16.f16.f32 "
                 "{%0,%1,%2,%3},{%4,%5,%6,%7},{%8,%9},{%0,%1,%2,%3};"
                 : "+f"(c[0]), "+f"(c[1]), "+f"(c[2]), "+f"(c[3])
                 : "r"(a[0]), "r"(a[1]), "r"(a[2]), "r"(a[3]), "r"(b[0]), "r"(b[1]));
}

// two-limb fp16 split of a float pair -> packed H and scaled-M half2s
__device__ __forceinline__ void cvt2(float a, float b, uint32_t& H, uint32_t& M) {
    __half2 h = __floats2half2_rn(a, b);
    float2 hf = __half22float2(h);
    __half2 m = __floats2half2_rn((a - hf.x) * SCALE, (b - hf.y) * SCALE);
    H = *reinterpret_cast<uint32_t*>(&h);
    M = *reinterpret_cast<uint32_t*>(&m);
}

// ---------------- prep: zero stats + split W into fp16 limbs ----------------
__global__ void prep_kernel(const float* __restrict__ W) {
    if (blockIdx.x == 0) {
        if (threadIdx.x == 0) { g_ent = 0.0f; g_conf = 0.0f; }
        if (threadIdx.x < NEXP) g_counts[threadIdx.x] = 0;
    }
    int i = (blockIdx.x * 256 + threadIdx.x) * 4;
    if (i < NEXP * DMODEL) {
        float4 f = *(const float4*)(W + i);
        uint32_t h0, m0, h1, m1;
        cvt2(f.x, f.y, h0, m0);
        cvt2(f.z, f.w, h1, m1);
        *(uint2*)(g_Wh + i) = make_uint2(h0, h1);
        *(uint2*)(g_Wm + i) = make_uint2(m0, m1);
    }
}

// ---------------- main fused router ----------------
__global__ __launch_bounds__(256)
void router_kernel(const float* __restrict__ x, float* __restrict__ out) {
    extern __shared__ __align__(16) char dsm[];
    __shared__ int hist[NEXP];

    const int t    = threadIdx.x;
    const int wid  = t >> 5;
    const int lane = t & 31;
    const int mbase = blockIdx.x * MT;
    const uint32_t smbase = smem_u32(dsm);

    if (t < NEXP) hist[t] = 0;

    // load-thread assignments
    const int xr  = t >> 1;          // token row 0..127
    const int xc  = (t & 1) * 16;    // 16-float half of the 32-k slice
    const int wr  = t >> 2;          // expert row 0..63
    const int wcb = (t & 3) * 8;     // 8-half chunk

    // warp tile: 4 m-warps x 2 n-warps, each M32 x N32
    const int wm = (wid >> 1) * 32;
    const int wn = (wid & 1) * 32;

    // per-lane ldmatrix byte offsets
    const uint32_t a_l_off = (uint32_t)((lane & 15) * ASTR + (lane >> 4) * 16);
    const uint32_t b_l_off = (uint32_t)(((lane & 7) + ((lane >> 4) & 1) * 8) * ASTR + ((lane >> 3) & 1) * 16);

    float c0[2][4][4], c1[2][4][4];
    #pragma unroll
    for (int i = 0; i < 2; i++)
        #pragma unroll
        for (int j = 0; j < 4; j++)
            #pragma unroll
            for (int k = 0; k < 4; k++) { c0[i][j][k] = 0.0f; c1[i][j][k] = 0.0f; }

    // prefetch tile 0
    float4 xv0, xv1, xv2, xv3;
    uint4 wvh, wvm;
    {
        const float* xp = x + (size_t)(mbase + xr) * DMODEL + xc;
        xv0 = ((const float4*)xp)[0]; xv1 = ((const float4*)xp)[1];
        xv2 = ((const float4*)xp)[2]; xv3 = ((const float4*)xp)[3];
        wvh = *(const uint4*)(g_Wh + (size_t)wr * DMODEL + wcb);
        wvm = *(const uint4*)(g_Wm + (size_t)wr * DMODEL + wcb);
    }

    for (int tile = 0; tile < KT; tile++) {
        const uint32_t bb = smbase + (tile & 1) * BUF_BYTES;

        // ---- convert staged x -> limbs, store; store W limbs ----
        {
            uint32_t H[8], M[8];
            cvt2(xv0.x, xv0.y, H[0], M[0]); cvt2(xv0.z, xv0.w, H[1], M[1]);
            cvt2(xv1.x, xv1.y, H[2], M[2]); cvt2(xv1.z, xv1.w, H[3], M[3]);
            cvt2(xv2.x, xv2.y, H[4], M[4]); cvt2(xv2.z, xv2.w, H[5], M[5]);
            cvt2(xv3.x, xv3.y, H[6], M[6]); cvt2(xv3.z, xv3.w, H[7], M[7]);
            uint32_t a0 = bb + AH_OFF + xr * ASTR + xc * 2;
            STS128(a0,      H[0], H[1], H[2], H[3]);
            STS128(a0 + 16, H[4], H[5], H[6], H[7]);
            uint32_t a1 = bb + AM_OFF + xr * ASTR + xc * 2;
            STS128(a1,      M[0], M[1], M[2], M[3]);
            STS128(a1 + 16, M[4], M[5], M[6], M[7]);
            uint32_t b0 = bb + BH_OFF + wr * ASTR + wcb * 2;
            STS128(b0, wvh.x, wvh.y, wvh.z, wvh.w);
            uint32_t b1 = bb + BM_OFF + wr * ASTR + wcb * 2;
            STS128(b1, wvm.x, wvm.y, wvm.z, wvm.w);
        }

        // ---- prefetch next tile ----
        if (tile + 1 < KT) {
            const float* xp = x + (size_t)(mbase + xr) * DMODEL + (tile + 1) * BK + xc;
            xv0 = ((const float4*)xp)[0]; xv1 = ((const float4*)xp)[1];
            xv2 = ((const float4*)xp)[2]; xv3 = ((const float4*)xp)[3];
            wvh = *(const uint4*)(g_Wh + (size_t)wr * DMODEL + (tile + 1) * BK + wcb);
            wvm = *(const uint4*)(g_Wm + (size_t)wr * DMODEL + (tile + 1) * BK + wcb);
        }

        __syncthreads();

        // ---- compute: 2 k16 steps, 3 limb products ----
        #pragma unroll
        for (int ks = 0; ks < 2; ks++) {
            uint32_t ah[2][4], am[2][4], bh[4][2], bm[4][2];
            #pragma unroll
            for (int mt = 0; mt < 2; mt++) {
                uint32_t ab = bb + (uint32_t)((wm + mt * 16) * ASTR) + a_l_off + ks * 32;
                ldsm4(ah[mt][0], ah[mt][1], ah[mt][2], ah[mt][3], ab + AH_OFF);
                ldsm4(am[mt][0], am[mt][1], am[mt][2], am[mt][3], ab + AM_OFF);
            }
            #pragma unroll
            for (int np = 0; np < 2; np++) {
                uint32_t nb = bb + (uint32_t)((wn + np * 16) * ASTR) + b_l_off + ks * 32;
                uint32_t r0, r1, r2, r3;
                ldsm4(r0, r1, r2, r3, nb + BH_OFF);
                bh[np*2][0] = r0; bh[np*2][1] = r1; bh[np*2+1][0] = r2; bh[np*2+1][1] = r3;
                ldsm4(r0, r1, r2, r3, nb + BM_OFF);
                bm[np*2][0] = r0; bm[np*2][1] = r1; bm[np*2+1][0] = r2; bm[np*2+1][1] = r3;
            }
            #pragma unroll
            for (int mt = 0; mt < 2; mt++)
                #pragma unroll
                for (int nt = 0; nt < 4; nt++) {
                    mma16816(c0[mt][nt], ah[mt], bh[nt]);
                    mma16816(c1[mt][nt], ah[mt], bm[nt]);
                    mma16816(c1[mt][nt], am[mt], bh[nt]);
                }
        }
    }

    // ---- dump combined logits to smem (overlay buffers) ----
    __syncthreads();
    float* Lsm = reinterpret_cast<float*>(dsm);
    #pragma unroll
    for (int mt = 0; mt < 2; mt++)
        #pragma unroll
        for (int nt = 0; nt < 4; nt++) {
            int r0 = wm + mt * 16 + (lane >> 2);
            int cc = wn + nt * 8 + (lane & 3) * 2;
            Lsm[r0 * LSTR + cc]           = c0[mt][nt][0] + c1[mt][nt][0] * INVS;
            Lsm[r0 * LSTR + cc + 1]       = c0[mt][nt][1] + c1[mt][nt][1] * INVS;
            Lsm[(r0 + 8) * LSTR + cc]     = c0[mt][nt][2] + c1[mt][nt][2] * INVS;
            Lsm[(r0 + 8) * LSTR + cc + 1] = c0[mt][nt][3] + c1[mt][nt][3] * INVS;
        }
    __syncthreads();

    // ---- per-token epilogue (threads 0..127) ----
    float ent = 0.0f, conf = 0.0f;
    if (t < MT) {
        const int tok = mbase + t;
        float* L = &Lsm[t * LSTR];

        // top-2 (strict > keeps lowest index on ties, matching jax)
        float m1 = -1e30f, m2 = -1e30f;
        int i1 = 0, i2 = 0;
        #pragma unroll
        for (int e = 0; e < NEXP; e++) {
            float v = L[e];
            if (v > m1)      { m2 = m1; i2 = i1; m1 = v; i1 = e; }
            else if (v > m2) { m2 = v;  i2 = e; }
        }

        float Z = 0.0f;
        #pragma unroll 8
        for (int e = 0; e < NEXP; e++) {
            float ex = __expf(L[e] - m1);
            L[e] = ex;
            Z += ex;
        }
        const float invZ = 1.0f / Z;

        float4* dst = reinterpret_cast<float4*>(out + OFF_P + (size_t)tok * NEXP);
        #pragma unroll 4
        for (int i = 0; i < 16; i++) {
            float p0 = L[4*i+0] * invZ;
            float p1 = L[4*i+1] * invZ;
            float p2 = L[4*i+2] * invZ;
            float p3 = L[4*i+3] * invZ;
            ent -= p0 * __logf(p0 + 1e-10f) + p1 * __logf(p1 + 1e-10f)
                 + p2 * __logf(p2 + 1e-10f) + p3 * __logf(p3 + 1e-10f);
            dst[i] = make_float4(p0, p1, p2, p3);
        }

        float ed = __expf(m2 - m1);
        float w0 = 1.0f / (1.0f + ed);
        float w1 = ed * w0;
        *reinterpret_cast<float2*>(out + OFF_W + (size_t)tok * 2) = make_float2(w0, w1);
        *reinterpret_cast<float2*>(out + OFF_I + (size_t)tok * 2) = make_float2((float)i1, (float)i2);
        conf = w0;

        atomicAdd(&hist[i1], 1);
        atomicAdd(&hist[i2], 1);

        #pragma unroll
        for (int o = 16; o > 0; o >>= 1) {
            ent  += __shfl_down_sync(0xffffffffu, ent,  o);
            conf += __shfl_down_sync(0xffffffffu, conf, o);
        }
        if (lane == 0) { atomicAdd(&g_ent, ent); atomicAdd(&g_conf, conf); }
    }

    __syncthreads();
    if (t < NEXP) { int c = hist[t]; if (c) atomicAdd(&g_counts[t], c); }
}

__global__ void finalize_kernel(float* __restrict__ out) {
    int t = threadIdx.x;
    if (t == 0) {
        out[OFF_ENT]  = g_ent  * (1.0f / 16384.0f);
        out[OFF_CONF] = g_conf * (1.0f / 16384.0f);
    }
    if (t < NEXP)
        out[OFF_UTIL + t] = (float)g_counts[t] * (1.0f / 32768.0f);
}

extern "C" void kernel_launch(void* const* d_in, const int* in_sizes, int n_in,
                              void* d_out, int out_size) {
    const float* x = (const float*)d_in[0];   // [4,4096,2048] fp32
    const float* W = (const float*)d_in[1];   // [64,2048] fp32
    float* out = (float*)d_out;

    static int configured = 0;
    if (!configured) {
        cudaFuncSetAttribute(router_kernel, cudaFuncAttributeMaxDynamicSharedMemorySize, DSM_BYTES);
        configured = 1;
    }

    prep_kernel<<<128, 256>>>(W);
    router_kernel<<<NCTAS, 256, DSM_BYTES>>>(x, out);
    finalize_kernel<<<1, 64>>>(out);
}